// round 10
// baseline (speedup 1.0000x reference)
#include <cuda_runtime.h>
#include <cstdint>

// Blur_82471962018173: depthwise 4x4 FIR on (4,128,513,513) fp32 -> (4,128,512,512)
// Separable: w_j = k[0][j], u_i = k[i][0]/k[0][0] (exact: rank-1 dyadic kernel).
//
// R10: software-pipelined ring staging. R9 (188us, DRAM 70%) serialized
// stage->wait->compute per CTA; DRAM duty was phase-gated. Here each CTA owns a
// 64-row strip walked in 8-row chunks over a 19-row smem ring (11 live + 8
// prefetch rows, exact). Per chunk: issue cp.async prefetch of next chunk,
// compute current chunk, then wait+bar. DRAM request stream is continuous.
// Same 39KB smem, 512 thr, 4 CTAs/SM -> full occupancy preserved.

#define W_IN  513
#define H_IN  513
#define W_OUT 512
#define H_OUT 512
#define STRIP 64
#define CHUNK 8
#define NCHUNK (STRIP / CHUNK)     // 8
#define RING  19                   // rows resident: 11 in-use + 8 prefetch
#define SROW  516                  // row pitch (16B-aligned slots)
#define NT    512

__device__ __forceinline__ void cp4(float* dst, const float* src) {
    unsigned s = (unsigned)__cvta_generic_to_shared(dst);
    asm volatile("cp.async.ca.shared.global [%0], [%1], 4;\n" :: "r"(s), "l"(src));
}

__global__ __launch_bounds__(NT, 4)
void blur_ring_kernel(const float* __restrict__ in,
                      const float* __restrict__ kern,
                      float* __restrict__ out)
{
    __shared__ __align__(16) float sm[RING * SROW];   // 39.2 KB

    const int img = blockIdx.y;
    const int Y0  = blockIdx.x * STRIP;
    const float* __restrict__ ip = in  + (size_t)img * (W_IN * H_IN);
    float* __restrict__       op = out + (size_t)img * (W_OUT * H_OUT);
    const int tid = threadIdx.x;

    // Separable factorization (uniform across threads)
    const float w0 = __ldg(kern + 0);
    const float w1 = __ldg(kern + 1);
    const float w2 = __ldg(kern + 2);
    const float w3 = __ldg(kern + 3);
    const float inv = 1.0f / w0;
    const float u1 = __ldg(kern + 4)  * inv;
    const float u2 = __ldg(kern + 8)  * inv;
    const float u3 = __ldg(kern + 12) * inv;   // u0 == 1

    // Stage input row gr into ring slot (gr+1) % RING. Rows outside [0,H_IN)
    // are zero-pad (plain STS; visible after the chunk barrier).
    auto stage_row = [&](int gr) {
        float* __restrict__ dst = sm + ((gr + 1) % RING) * SROW;
        if ((unsigned)gr < (unsigned)H_IN) {
            const float* __restrict__ src = ip + (size_t)gr * W_IN;
            for (int xx = tid; xx < W_IN; xx += NT)
                cp4(dst + xx, src + xx);
        } else {
            for (int xx = tid; xx < W_IN; xx += NT)
                dst[xx] = 0.f;
        }
    };

    // One output column per thread.
    const int x = tid;
    const bool lok = (x > 0);
    const bool rok = (x < W_OUT - 1);

    // Horizontally-filtered value of input row gr at column x.
    auto hr = [&](int gr) -> float {
        const float* __restrict__ row = sm + ((gr + 1) % RING) * SROW + x;
        const float a0 = lok ? row[-1] : 0.f;
        const float a1 = row[0];
        const float a2 = row[1];
        const float a3 = rok ? row[2] : 0.f;
        return fmaf(w0, a0, fmaf(w1, a1, fmaf(w2, a2, w3 * a3)));
    };

    // ---- Prologue: stage rows Y0-1 .. Y0+9 (covers chunk 0).
    #pragma unroll
    for (int r = -1; r <= 9; ++r) stage_row(Y0 + r);
    asm volatile("cp.async.commit_group;\n" ::: "memory");
    asm volatile("cp.async.wait_group 0;\n" ::: "memory");
    __syncthreads();

    // Vertical streaming ring (registers), continuous across chunks.
    float h0 = hr(Y0 - 1);
    float h1 = hr(Y0);
    float h2 = hr(Y0 + 1);

    for (int c = 0; c < NCHUNK; ++c) {
        // Prefetch next chunk's 8 new rows (skipped on last chunk).
        if (c + 1 < NCHUNK) {
            const int base = Y0 + CHUNK * c + 10;
            #pragma unroll
            for (int r = 0; r < CHUNK; ++r) stage_row(base + r);
            asm volatile("cp.async.commit_group;\n" ::: "memory");
        }

        // Compute current chunk while the prefetch is in flight.
        float* __restrict__ orow = op + (size_t)(Y0 + CHUNK * c) * W_OUT + x;
        #pragma unroll
        for (int r = 0; r < CHUNK; ++r) {
            const int y = Y0 + CHUNK * c + r;
            const float h3 = hr(y + 2);
            float o = fmaf(u1, h1, h0);
            o = fmaf(u2, h2, o);
            o = fmaf(u3, h3, o);
            orow[(size_t)r * W_OUT] = o;
            h0 = h1; h1 = h2; h2 = h3;
        }

        // Prefetched rows landed; all threads done with the retiring window.
        asm volatile("cp.async.wait_group 0;\n" ::: "memory");
        __syncthreads();
    }
}

extern "C" void kernel_launch(void* const* d_in, const int* in_sizes, int n_in,
                              void* d_out, int out_size)
{
    (void)n_in; (void)out_size;
    const float* input  = (const float*)d_in[0];
    const float* kernel = (const float*)d_in[1];
    float*       output = (float*)d_out;

    const int n_images = in_sizes[0] / (W_IN * H_IN);   // N*C = 512

    dim3 block(NT, 1, 1);
    dim3 grid(H_OUT / STRIP, n_images, 1);              // (8, 512)
    blur_ring_kernel<<<grid, block>>>(input, kernel, output);
}

// round 11
// speedup vs baseline: 1.1563x; 1.1563x over previous
#include <cuda_runtime.h>
#include <cstdint>

// Blur_82471962018173: depthwise 4x4 FIR on (4,128,513,513) fp32 -> (4,128,512,512)
// Separable: w_j = k[0][j], u_i = k[i][0]/k[0][0] (exact: rank-1 dyadic kernel).
//
// R11 = R9 (188us, DRAM 70%) + split-wait pipelining. R10's ring regressed
// (issue-bound: runtime %19 + 4B cp.async). Here: identical flat 19-row stage
// with all loads issued up-front, but committed as TWO cp.async groups:
//   A = rows [Y0-1, Y0+9]  -> wait_group 1 -> compute out rows 0..7
//   B = rows [Y0+10,Y0+17] -> wait_group 0 -> compute out rows 8..15
// Group B's DRAM latency hides behind compute of the first half; CTAs retire
// earlier -> higher DRAM duty. Same 39KB smem / 512 thr / 4 CTAs/SM.

#define W_IN  513
#define H_IN  513
#define W_OUT 512
#define H_OUT 512
#define TILE_ROWS 16
#define IN_ROWS   (TILE_ROWS + 3)          // 19 staged input rows
#define STAGE_FLOATS (IN_ROWS * W_IN)      // 9747
#define SMEM_FLOATS  (STAGE_FLOATS + 8)    // + shift(<=3) + pad
#define NT 512

__global__ __launch_bounds__(NT, 4)
void blur_split_kernel(const float* __restrict__ in,
                       const float* __restrict__ kern,
                       float* __restrict__ out)
{
    __shared__ __align__(16) float sm[SMEM_FLOATS];

    const int img = blockIdx.y;
    const int y0  = blockIdx.x * TILE_ROWS;
    const long gbase = (long)img * (W_IN * H_IN);
    float* __restrict__ op = out + (size_t)img * (W_OUT * H_OUT);
    const int tid = threadIdx.x;

    // Separable factorization (uniform across threads)
    const float w0 = __ldg(kern + 0);
    const float w1 = __ldg(kern + 1);
    const float w2 = __ldg(kern + 2);
    const float w3 = __ldg(kern + 3);
    const float inv = 1.0f / w0;
    const float u1 = __ldg(kern + 4)  * inv;
    const float u2 = __ldg(kern + 8)  * inv;
    const float u3 = __ldg(kern + 12) * inv;   // u0 == 1

    // ---- Flat staged region, ABSOLUTE offsets from tensor base `in`
    // (allocation-aligned; absolute flat idx ≡ 0 mod 4 => 16B aligned).
    // smem[i] holds absolute flat position aorg + i - shift.
    const int  r_lo = y0 - 1;
    const long aorg = gbase + (long)r_lo * W_IN;          // may be -513 (img 0)
    const int  shift = (int)(((aorg % 4) + 4) & 3);
    const int  v_lo = (r_lo < 0) ? 0 : r_lo;
    const int  v_hi = (y0 + IN_ROWS - 1 < H_IN) ? (y0 + IN_ROWS - 1) : H_IN;
    const long aflat_lo = gbase + (long)v_lo * W_IN;      // first valid abs idx
    const long aflat_hi = gbase + (long)v_hi * W_IN;      // one past last valid
    const long amid     = gbase + (long)(y0 + 10) * W_IN; // group A/B boundary
    const int  s_lo = (int)(aflat_lo - aorg) + shift;
    const int  s_hi = (int)(aflat_hi - aorg) + shift;

    // Zero-fill smem head/tail (nonempty only for first/last row-tiles).
    // Head belongs to window A, tail to window B; both visible at the syncs.
    for (int i = tid; i < s_lo; i += NT) sm[i] = 0.f;
    for (int i = s_hi + tid; i < STAGE_FLOATS + shift; i += NT) sm[i] = 0.f;

    // Stage [lo, hi): scalar head/tail (<=3 floats), 16B cp.async interior.
    auto stage_range = [&](long lo, long hi) {
        const long a0 = (lo + 3) & ~3L;
        const long a1 = hi & ~3L;
        for (long f = lo + tid; f < a0; f += NT)
            sm[(int)(f - aorg) + shift] = __ldg(in + f);
        for (long f = a1 + tid; f < hi; f += NT)
            sm[(int)(f - aorg) + shift] = __ldg(in + f);
        const unsigned int n4 = (unsigned int)((a1 - a0) >> 2);
        const float4* __restrict__ gsrc = reinterpret_cast<const float4*>(in + a0);
        const unsigned int sbase =
            (unsigned int)__cvta_generic_to_shared(sm + ((int)(a0 - aorg) + shift));
        for (unsigned int i = (unsigned int)tid; i < n4; i += NT) {
            asm volatile("cp.async.cg.shared.global [%0], [%1], 16;\n"
                         :: "r"(sbase + i * 16u), "l"(gsrc + i));
        }
        asm volatile("cp.async.commit_group;\n" ::: "memory");
    };

    stage_range(aflat_lo, amid);   // group A: rows y0-1 .. y0+9
    stage_range(amid, aflat_hi);   // group B: rows y0+10 .. y0+17

    // ---- Compute: one output column per thread, split 8 + 8 rows.
    const int x   = tid;
    const bool lok = (x > 0);
    const bool rok = (x < W_OUT - 1);
    const float* __restrict__ sb = sm + shift + x;

    auto hrow = [&](int lr) -> float {
        const float* __restrict__ row = sb + lr * W_IN;
        const float a0 = lok ? row[-1] : 0.f;
        const float a1 = row[0];
        const float a2 = row[1];
        const float a3 = rok ? row[2] : 0.f;
        return fmaf(w0, a0, fmaf(w1, a1, fmaf(w2, a2, w3 * a3)));
    };

    // Wait for group A only (B still in flight), then compute rows 0..7
    // (need staged rows 0..10 = lr 0..10, all in A).
    asm volatile("cp.async.wait_group 1;\n" ::: "memory");
    __syncthreads();

    float h0 = hrow(0);
    float h1 = hrow(1);
    float h2 = hrow(2);

    float* __restrict__ orow = op + (size_t)y0 * W_OUT + x;
    #pragma unroll
    for (int r = 0; r < 8; ++r) {
        const float h3 = hrow(r + 3);
        float o = fmaf(u1, h1, h0);
        o = fmaf(u2, h2, o);
        o = fmaf(u3, h3, o);
        orow[(size_t)r * W_OUT] = o;
        h0 = h1; h1 = h2; h2 = h3;
    }

    // Group B landed (mostly) while we computed; finish rows 8..15.
    asm volatile("cp.async.wait_group 0;\n" ::: "memory");
    __syncthreads();

    #pragma unroll
    for (int r = 8; r < TILE_ROWS; ++r) {
        const float h3 = hrow(r + 3);
        float o = fmaf(u1, h1, h0);
        o = fmaf(u2, h2, o);
        o = fmaf(u3, h3, o);
        orow[(size_t)r * W_OUT] = o;
        h0 = h1; h1 = h2; h2 = h3;
    }
}

extern "C" void kernel_launch(void* const* d_in, const int* in_sizes, int n_in,
                              void* d_out, int out_size)
{
    (void)n_in; (void)out_size;
    const float* input  = (const float*)d_in[0];
    const float* kernel = (const float*)d_in[1];
    float*       output = (float*)d_out;

    const int n_images = in_sizes[0] / (W_IN * H_IN);   // N*C = 512

    dim3 block(NT, 1, 1);
    dim3 grid(H_OUT / TILE_ROWS, n_images, 1);          // (32, 512)
    blur_split_kernel<<<grid, block>>>(input, kernel, output);
}